// round 5
// baseline (speedup 1.0000x reference)
#include <cuda_runtime.h>
#include <cmath>

static constexpr int B_    = 256;
static constexpr int TR_   = 512;
static constexpr int P_    = 128;
static constexpr int H_    = 128;
static constexpr int TA_   = 64;
static constexpr int PSTD_ = 32;
static constexpr int PSTA_ = 16;
static constexpr int HH_   = 64;                 // head hidden
static constexpr int FD_   = H_ + PSTD_ + PSTA_; // 176

// ---------------- scratch (device global: allocation-free) ----------------
// layout (floats):
//   xhat  : [131072,128]  @ 0          (16,777,216)
//   inp   : [131072,256]  @ 16777216   (33,554,432)   = [x_dec | m]
//   htil  : [131072,128]  @ 50331648   (16,777,216)
//   gi    : [131072,384]  @ 67108864   (50,331,648)
//   delta : [131072,128]  @ 117440512  (16,777,216)
__device__ float g_scratch[134217728];

__device__ __forceinline__ float sigmoidf_(float x) { return 1.f / (1.f + expf(-x)); }

// ---------------------------------------------------------------------------
// Phase 0: elementwise prep.  delta = 1/(1+e^dt) (== exp(-softplus(dt)))
// ---------------------------------------------------------------------------
__global__ __launch_bounds__(256) void prep_kernel(
    const float* __restrict__ X, const float* __restrict__ M,
    const float* __restrict__ DT, const float* __restrict__ xmean,
    float* __restrict__ delta, float* __restrict__ xhat, float* __restrict__ inp)
{
    int i4 = blockIdx.x * blockDim.x + threadIdx.x;   // 0 .. 4194303 (float4 idx)
    const float4 x4 = reinterpret_cast<const float4*>(X)[i4];
    const float4 m4 = reinterpret_cast<const float4*>(M)[i4];
    const float4 t4 = reinterpret_cast<const float4*>(DT)[i4];
    int row = i4 >> 5;        // /32 float4 per 128-col row
    int c4  = i4 & 31;
    const float4 xm4 = reinterpret_cast<const float4*>(xmean)[c4];

    float4 d4, xh4, xd4;
#pragma unroll
    for (int c = 0; c < 4; c++) {
        float x  = ((const float*)&x4)[c];
        float m  = ((const float*)&m4)[c];
        float dt = ((const float*)&t4)[c];
        float xm = ((const float*)&xm4)[c];
        float d  = 1.f / (1.f + expf(dt));
        float xh = m * x + (1.f - m) * xm;
        float xd = m * x + (1.f - m) * (d * xh + (1.f - d) * xm);
        ((float*)&d4)[c]  = d;
        ((float*)&xh4)[c] = xh;
        ((float*)&xd4)[c] = xd;
    }
    reinterpret_cast<float4*>(delta)[i4] = d4;
    reinterpret_cast<float4*>(xhat)[i4]  = xh4;
    reinterpret_cast<float4*>(inp)[row * 64 + c4]      = xd4;  // x_dec
    reinterpret_cast<float4*>(inp)[row * 64 + 32 + c4] = m4;   // m
}

// ---------------------------------------------------------------------------
// Phase 1: C[M,N] = A[M,K] @ Bw[N,K]^T + bias ; EPI=1 -> tanh epilogue
// BM=BN=128, BK=16, 256 threads, 8x8 microtile.  All dims divide tiles.
// ---------------------------------------------------------------------------
template <int EPI>
__global__ __launch_bounds__(256) void sgemm_tn(
    const float* __restrict__ A, const float* __restrict__ Bw,
    const float* __restrict__ bias, float* __restrict__ C,
    int M, int N, int K)
{
    constexpr int BK = 16;
    __shared__ float As[BK][128];
    __shared__ float Bs[BK][128];

    const int bm = blockIdx.y * 128;
    const int bn = blockIdx.x * 128;
    const int tid = threadIdx.x;
    const int tr = (tid >> 4) << 3;       // 0..120
    const int tc = (tid & 15) << 3;       // 0..120
    const int lRow = tid >> 2;            // 0..63
    const int lCol = (tid & 3) << 2;      // 0,4,8,12

    float acc[8][8];
#pragma unroll
    for (int i = 0; i < 8; i++)
#pragma unroll
        for (int j = 0; j < 8; j++) acc[i][j] = 0.f;

    const float* Aptr = A + (size_t)bm * K;
    const float* Bptr = Bw + (size_t)bn * K;

    for (int k0 = 0; k0 < K; k0 += BK) {
#pragma unroll
        for (int h = 0; h < 2; h++) {
            int r = lRow + h * 64;
            float4 va = *reinterpret_cast<const float4*>(Aptr + (size_t)r * K + k0 + lCol);
            As[lCol + 0][r] = va.x; As[lCol + 1][r] = va.y;
            As[lCol + 2][r] = va.z; As[lCol + 3][r] = va.w;
            float4 vb = *reinterpret_cast<const float4*>(Bptr + (size_t)r * K + k0 + lCol);
            Bs[lCol + 0][r] = vb.x; Bs[lCol + 1][r] = vb.y;
            Bs[lCol + 2][r] = vb.z; Bs[lCol + 3][r] = vb.w;
        }
        __syncthreads();
#pragma unroll
        for (int k = 0; k < BK; k++) {
            float ar[8], bc[8];
            *(float4*)&ar[0] = *(const float4*)&As[k][tr];
            *(float4*)&ar[4] = *(const float4*)&As[k][tr + 4];
            *(float4*)&bc[0] = *(const float4*)&Bs[k][tc];
            *(float4*)&bc[4] = *(const float4*)&Bs[k][tc + 4];
#pragma unroll
            for (int i = 0; i < 8; i++)
#pragma unroll
                for (int j = 0; j < 8; j++) acc[i][j] += ar[i] * bc[j];
        }
        __syncthreads();
    }

    float bv[8];
    *(float4*)&bv[0] = *(const float4*)&bias[bn + tc];
    *(float4*)&bv[4] = *(const float4*)&bias[bn + tc + 4];
#pragma unroll
    for (int i = 0; i < 8; i++) {
        float o[8];
#pragma unroll
        for (int j = 0; j < 8; j++) {
            float v = acc[i][j] + bv[j];
            o[j] = EPI ? tanhf(v) : v;
        }
        float* crow = C + (size_t)(bm + tr + i) * N + bn + tc;
        *(float4*)&crow[0] = *(float4*)&o[0];
        *(float4*)&crow[4] = *(float4*)&o[4];
    }
}

// ---------------------------------------------------------------------------
// Phase 2: sequential GRU recurrence.
// 128 CTAs x 128 threads; CTA owns 2 batch rows; thread j owns h[r][j].
// Whh (transposed, [gate][k][j]) lives in 192KB smem; h' broadcast via smem.
// gi/delta/htil for step t+1 are software-prefetched during step t's k-loop.
// ---------------------------------------------------------------------------
__global__ __launch_bounds__(128) void recurrence_kernel(
    const float* __restrict__ gi, const float* __restrict__ delta,
    const float* __restrict__ htil, const float* __restrict__ Whh,
    const float* __restrict__ bhh, float* __restrict__ Hraw)
{
    extern __shared__ float sm[];
    float* Ws = sm;            // [3][128][128]: Ws[g*16384 + k*128 + j]
    float* hp = sm + 49152;    // [2][128]
    const int j  = threadIdx.x;
    const int b0 = blockIdx.x * 2;
    const int b1 = b0 + 1;

    // load Whh (coalesced global), store transposed
    for (int s = j; s < 3 * 128 * 128; s += 128) {
        int n = s >> 7, k = s & 127;
        int g = n >> 7, row = n & 127;
        Ws[g * 16384 + k * 128 + row] = Whh[s];
    }
    const float br = bhh[j], bz = bhh[H_ + j], bn = bhh[2 * H_ + j];
    float h0 = 0.f, h1 = 0.f;
    __syncthreads();

    const float* Wr = Ws + j;
    const float* Wz = Ws + 16384 + j;
    const float* Wn = Ws + 32768 + j;

    const size_t base0 = (size_t)b0 * TR_;
    const size_t base1 = (size_t)b1 * TR_;

    // prefetch t = 0
    float d0 = delta[base0 * 128 + j], d1 = delta[base1 * 128 + j];
    float ht0 = htil[base0 * 128 + j], ht1 = htil[base1 * 128 + j];
    float ir0 = gi[base0 * 384 + j],       iz0 = gi[base0 * 384 + 128 + j], in0 = gi[base0 * 384 + 256 + j];
    float ir1 = gi[base1 * 384 + j],       iz1 = gi[base1 * 384 + 128 + j], in1 = gi[base1 * 384 + 256 + j];

    for (int t = 0; t < TR_; t++) {
        const float cd0 = d0, cd1 = d1, cht0 = ht0, cht1 = ht1;
        const float cir0 = ir0, ciz0 = iz0, cin0 = in0;
        const float cir1 = ir1, ciz1 = iz1, cin1 = in1;

        const float hp0 = cd0 * h0 + (1.f - cd0) * cht0;
        const float hp1 = cd1 * h1 + (1.f - cd1) * cht1;
        hp[j] = hp0;
        hp[128 + j] = hp1;
        __syncthreads();

        // prefetch t+1 (clamped; values unused on last iter)
        {
            int tn = (t + 1 < TR_) ? t + 1 : t;
            size_t p0 = base0 + tn, p1 = base1 + tn;
            d0 = delta[p0 * 128 + j]; d1 = delta[p1 * 128 + j];
            ht0 = htil[p0 * 128 + j]; ht1 = htil[p1 * 128 + j];
            ir0 = gi[p0 * 384 + j]; iz0 = gi[p0 * 384 + 128 + j]; in0 = gi[p0 * 384 + 256 + j];
            ir1 = gi[p1 * 384 + j]; iz1 = gi[p1 * 384 + 128 + j]; in1 = gi[p1 * 384 + 256 + j];
        }

        float ar0 = 0.f, az0 = 0.f, an0 = 0.f, ar1 = 0.f, az1 = 0.f, an1 = 0.f;
#pragma unroll
        for (int k4 = 0; k4 < 128; k4 += 4) {
            float4 a0 = *reinterpret_cast<const float4*>(&hp[k4]);
            float4 a1 = *reinterpret_cast<const float4*>(&hp[128 + k4]);
#pragma unroll
            for (int kk = 0; kk < 4; kk++) {
                float wr = Wr[(k4 + kk) * 128];
                float wz = Wz[(k4 + kk) * 128];
                float wn = Wn[(k4 + kk) * 128];
                float a0v = ((const float*)&a0)[kk];
                float a1v = ((const float*)&a1)[kk];
                ar0 += a0v * wr; az0 += a0v * wz; an0 += a0v * wn;
                ar1 += a1v * wr; az1 += a1v * wz; an1 += a1v * wn;
            }
        }
        __syncthreads();   // hp fully consumed before next step overwrites

        float r0 = sigmoidf_(cir0 + ar0 + br);
        float z0 = sigmoidf_(ciz0 + az0 + bz);
        float n0 = tanhf(cin0 + r0 * (an0 + bn));
        h0 = (1.f - z0) * n0 + z0 * hp0;

        float r1 = sigmoidf_(cir1 + ar1 + br);
        float z1 = sigmoidf_(ciz1 + az1 + bz);
        float n1 = tanhf(cin1 + r1 * (an1 + bn));
        h1 = (1.f - z1) * n1 + z1 * hp1;

        Hraw[(base0 + t) * 128 + j] = h0;
        Hraw[(base1 + t) * 128 + j] = h1;
    }
}

// ---------------------------------------------------------------------------
// Phase 3: gather + head MLP.  One warp per (b, ta); 8 warps/CTA share W1.
// ---------------------------------------------------------------------------
__global__ __launch_bounds__(256) void gather_head_kernel(
    const float* __restrict__ Hraw, const float* __restrict__ STD,
    const float* __restrict__ Z, const int* __restrict__ idx_map,
    const float* __restrict__ W1, const float* __restrict__ b1,
    const float* __restrict__ W2,
    float* __restrict__ eta, float* __restrict__ Hagg, float* __restrict__ maskO)
{
    extern __shared__ float sh[];
    float* W1s   = sh;                    // 64*176
    float* b1s   = W1s + HH_ * FD_;       // 64
    float* W2s   = b1s + HH_;             // 64
    float* feats = W2s + HH_;             // 8 * 184 (padded)

    const int tid = threadIdx.x;
    for (int s = tid; s < HH_ * FD_; s += 256) W1s[s] = W1[s];
    if (tid < HH_) { b1s[tid] = b1[tid]; W2s[tid] = W2[tid]; }
    __syncthreads();

    const int w = tid >> 5, lane = tid & 31;
    const int pair = blockIdx.x * 8 + w;      // 0 .. 16383
    const int b = pair >> 6, ta = pair & 63;

    const int idx = idx_map[b * TA_ + ta];
    const bool msk = idx >= 0;
    const int is = msk ? idx : 0;

    float* f = feats + w * 184;
    const float* hsrc = Hraw + ((size_t)b * TR_ + is) * H_;
    float4 hv = reinterpret_cast<const float4*>(hsrc)[lane];
    if (!msk) { hv.x = 0.f; hv.y = 0.f; hv.z = 0.f; hv.w = 0.f; }
    reinterpret_cast<float4*>(Hagg + ((size_t)b * TA_ + ta) * H_)[lane] = hv;
    reinterpret_cast<float4*>(f)[lane] = hv;
    f[128 + lane] = STD[(b * TA_ + ta) * PSTD_ + lane];
    if (lane < PSTA_) f[160 + lane] = Z[b * PSTA_ + lane];
    __syncwarp();

    float partial = 0.f;
#pragma unroll
    for (int jj0 = 0; jj0 < HH_; jj0 += 32) {
        int jj = jj0 + lane;
        float s = b1s[jj];
        const float* wrow = &W1s[jj * FD_];
#pragma unroll 8
        for (int k = 0; k < FD_; k++) s += f[k] * wrow[k];
        s = fmaxf(s, 0.f);
        partial += s * W2s[jj];
    }
#pragma unroll
    for (int o = 16; o; o >>= 1) partial += __shfl_xor_sync(0xffffffffu, partial, o);
    if (lane == 0) {
        eta[pair]   = partial;
        maskO[pair] = msk ? 1.f : 0.f;
    }
}

// ---------------------------------------------------------------------------
extern "C" void kernel_launch(void* const* d_in, const int* in_sizes, int n_in,
                              void* d_out, int out_size)
{
    const float* X     = (const float*)d_in[0];
    const float* M     = (const float*)d_in[1];
    const float* DT    = (const float*)d_in[2];
    const float* STD   = (const float*)d_in[3];
    const float* Z     = (const float*)d_in[4];
    const int*   idxm  = (const int*)  d_in[5];
    const float* xmean = (const float*)d_in[6];
    const float* Wd    = (const float*)d_in[7];
    const float* bd    = (const float*)d_in[8];
    const float* Wih   = (const float*)d_in[9];
    const float* bih   = (const float*)d_in[10];
    const float* Whh   = (const float*)d_in[11];
    const float* bhh   = (const float*)d_in[12];
    const float* W1    = (const float*)d_in[13];
    const float* b1    = (const float*)d_in[14];
    const float* W2    = (const float*)d_in[15];

    float* out   = (float*)d_out;
    float* eta   = out;                                    // 16384
    float* Hraw  = out + 16384;                            // 16,777,216
    float* Hagg  = out + 16384 + 16777216;                 // 2,097,152
    float* maskO = out + 16384 + 16777216 + 2097152;       // 16384

    float* scratch = nullptr;
    cudaGetSymbolAddress((void**)&scratch, g_scratch);
    float* xhat  = scratch;
    float* inp   = scratch + 16777216;
    float* htil  = scratch + 50331648;
    float* gi    = scratch + 67108864;
    float* delta = scratch + 117440512;

    // Phase 0
    prep_kernel<<<16384, 256>>>(X, M, DT, xmean, delta, xhat, inp);

    // Phase 1
    sgemm_tn<1><<<dim3(1, 1024), 256>>>(xhat, Wd, bd, htil, 131072, 128, 128);
    sgemm_tn<0><<<dim3(3, 1024), 256>>>(inp, Wih, bih, gi, 131072, 384, 256);

    // Phase 2
    const int rec_smem = (3 * 128 * 128 + 2 * 128) * (int)sizeof(float); // 197,632 B
    cudaFuncSetAttribute(recurrence_kernel,
                         cudaFuncAttributeMaxDynamicSharedMemorySize, rec_smem);
    recurrence_kernel<<<128, 128, rec_smem>>>(gi, delta, htil, Whh, bhh, Hraw);

    // Phase 3
    const int gh_smem = (HH_ * FD_ + HH_ + HH_ + 8 * 184) * (int)sizeof(float); // 51,456 B
    cudaFuncSetAttribute(gather_head_kernel,
                         cudaFuncAttributeMaxDynamicSharedMemorySize, gh_smem);
    gather_head_kernel<<<2048, 256, gh_smem>>>(Hraw, STD, Z, idxm, W1, b1, W2,
                                               eta, Hagg, maskO);
}

// round 8
// speedup vs baseline: 1.3915x; 1.3915x over previous
#include <cuda_runtime.h>
#include <cmath>

static constexpr int B_    = 256;
static constexpr int TR_   = 512;
static constexpr int H_    = 128;
static constexpr int TA_   = 64;
static constexpr int PSTD_ = 32;
static constexpr int PSTA_ = 16;
static constexpr int HH_   = 64;                 // head hidden
static constexpr int FD_   = H_ + PSTD_ + PSTA_; // 176

typedef unsigned long long ull;

// ---------------- packed-f32x2 helpers (dual-rate fp32 pipe) ----------------
__device__ __forceinline__ ull fma2_(ull a, ull b, ull c) {
    ull d;
    asm("fma.rn.f32x2 %0, %1, %2, %3;" : "=l"(d) : "l"(a), "l"(b), "l"(c));
    return d;
}
__device__ __forceinline__ ull splat2_(float x) {
    unsigned u = __float_as_uint(x);
    ull r;
    asm("mov.b64 %0, {%1, %1};" : "=l"(r) : "r"(u));
    return r;
}
__device__ __forceinline__ float2 unpack2_(ull v) {
    unsigned l, h;
    asm("mov.b64 {%0, %1}, %2;" : "=r"(l), "=r"(h) : "l"(v));
    return make_float2(__uint_as_float(l), __uint_as_float(h));
}

// ---------------- scratch (device global: allocation-free) ----------------
//   xhat  : [131072,128]  @ 0
//   inp   : [131072,256]  @ 16777216
//   htil  : [131072,128]  @ 50331648
//   gi    : [131072,384]  @ 67108864
//   delta : [131072,128]  @ 117440512
__device__ float g_scratch[134217728];

__device__ __forceinline__ float sigmoidf_(float x) { return 1.f / (1.f + expf(-x)); }

// ---------------------------------------------------------------------------
// Phase 0: elementwise prep.  delta = 1/(1+e^dt) (== exp(-softplus(dt)))
// ---------------------------------------------------------------------------
__global__ __launch_bounds__(256) void prep_kernel(
    const float* __restrict__ X, const float* __restrict__ M,
    const float* __restrict__ DT, const float* __restrict__ xmean,
    float* __restrict__ delta, float* __restrict__ xhat, float* __restrict__ inp)
{
    int i4 = blockIdx.x * blockDim.x + threadIdx.x;   // float4 index
    const float4 x4 = reinterpret_cast<const float4*>(X)[i4];
    const float4 m4 = reinterpret_cast<const float4*>(M)[i4];
    const float4 t4 = reinterpret_cast<const float4*>(DT)[i4];
    int row = i4 >> 5;
    int c4  = i4 & 31;
    const float4 xm4 = reinterpret_cast<const float4*>(xmean)[c4];

    float4 d4, xh4, xd4;
#pragma unroll
    for (int c = 0; c < 4; c++) {
        float x  = ((const float*)&x4)[c];
        float m  = ((const float*)&m4)[c];
        float dt = ((const float*)&t4)[c];
        float xm = ((const float*)&xm4)[c];
        float d  = 1.f / (1.f + expf(dt));
        float xh = m * x + (1.f - m) * xm;
        float xd = m * x + (1.f - m) * (d * xh + (1.f - d) * xm);
        ((float*)&d4)[c]  = d;
        ((float*)&xh4)[c] = xh;
        ((float*)&xd4)[c] = xd;
    }
    reinterpret_cast<float4*>(delta)[i4] = d4;
    reinterpret_cast<float4*>(xhat)[i4]  = xh4;
    reinterpret_cast<float4*>(inp)[row * 64 + c4]      = xd4;  // x_dec
    reinterpret_cast<float4*>(inp)[row * 64 + 32 + c4] = m4;   // m
}

// ---------------------------------------------------------------------------
// Phase 1: C[M,N] = A[M,K] @ Bw[N,K]^T + bias ; EPI=1 -> tanh epilogue
// BM=BN=128, BK=16, 256 threads, 8x8 microtile, f32x2 packed over row-pairs.
// ---------------------------------------------------------------------------
template <int EPI>
__global__ __launch_bounds__(256, 2) void sgemm2(
    const float* __restrict__ A, const float* __restrict__ Bw,
    const float* __restrict__ bias, float* __restrict__ C,
    int M, int N, int K)
{
    constexpr int BK = 16;
    __shared__ float As[BK][128];
    __shared__ float Bs[BK][128];

    const int bm = blockIdx.y * 128;
    const int bn = blockIdx.x * 128;
    const int tid = threadIdx.x;
    const int tr = (tid >> 4) << 3;       // 0..120 (mult of 8 -> 16B aligned)
    const int tc = (tid & 15) << 3;       // 0..120
    const int lRow = tid >> 2;            // 0..63
    const int lCol = (tid & 3) << 2;      // 0,4,8,12

    ull acc[4][8];                        // acc[i2][j] packs rows (tr+2*i2, tr+2*i2+1)
#pragma unroll
    for (int i = 0; i < 4; i++)
#pragma unroll
        for (int j = 0; j < 8; j++) acc[i][j] = 0ull;

    const float* Aptr = A + (size_t)bm * K;
    const float* Bptr = Bw + (size_t)bn * K;

    for (int k0 = 0; k0 < K; k0 += BK) {
#pragma unroll
        for (int h = 0; h < 2; h++) {
            int r = lRow + h * 64;
            float4 va = *reinterpret_cast<const float4*>(Aptr + (size_t)r * K + k0 + lCol);
            As[lCol + 0][r] = va.x; As[lCol + 1][r] = va.y;
            As[lCol + 2][r] = va.z; As[lCol + 3][r] = va.w;
            float4 vb = *reinterpret_cast<const float4*>(Bptr + (size_t)r * K + k0 + lCol);
            Bs[lCol + 0][r] = vb.x; Bs[lCol + 1][r] = vb.y;
            Bs[lCol + 2][r] = vb.z; Bs[lCol + 3][r] = vb.w;
        }
        __syncthreads();
#pragma unroll
        for (int k = 0; k < BK; k++) {
            // row pairs come packed straight out of the LDS.128s
            ulonglong2 aP0 = *reinterpret_cast<const ulonglong2*>(&As[k][tr]);
            ulonglong2 aP1 = *reinterpret_cast<const ulonglong2*>(&As[k][tr + 4]);
            float4 b0 = *reinterpret_cast<const float4*>(&Bs[k][tc]);
            float4 b1 = *reinterpret_cast<const float4*>(&Bs[k][tc + 4]);
            ull bb[8];
            bb[0] = splat2_(b0.x); bb[1] = splat2_(b0.y);
            bb[2] = splat2_(b0.z); bb[3] = splat2_(b0.w);
            bb[4] = splat2_(b1.x); bb[5] = splat2_(b1.y);
            bb[6] = splat2_(b1.z); bb[7] = splat2_(b1.w);
#pragma unroll
            for (int j = 0; j < 8; j++) {
                acc[0][j] = fma2_(aP0.x, bb[j], acc[0][j]);
                acc[1][j] = fma2_(aP0.y, bb[j], acc[1][j]);
                acc[2][j] = fma2_(aP1.x, bb[j], acc[2][j]);
                acc[3][j] = fma2_(aP1.y, bb[j], acc[3][j]);
            }
        }
        __syncthreads();
    }

    float bv[8];
    *(float4*)&bv[0] = *(const float4*)&bias[bn + tc];
    *(float4*)&bv[4] = *(const float4*)&bias[bn + tc + 4];
#pragma unroll
    for (int i2 = 0; i2 < 4; i2++) {
        float oL[8], oH[8];
#pragma unroll
        for (int j = 0; j < 8; j++) {
            float2 p = unpack2_(acc[i2][j]);
            float vl = p.x + bv[j];
            float vh = p.y + bv[j];
            oL[j] = EPI ? tanhf(vl) : vl;
            oH[j] = EPI ? tanhf(vh) : vh;
        }
        float* crowL = C + (size_t)(bm + tr + 2 * i2 + 0) * N + bn + tc;
        float* crowH = C + (size_t)(bm + tr + 2 * i2 + 1) * N + bn + tc;
        *(float4*)&crowL[0] = *(float4*)&oL[0];
        *(float4*)&crowL[4] = *(float4*)&oL[4];
        *(float4*)&crowH[0] = *(float4*)&oH[0];
        *(float4*)&crowH[4] = *(float4*)&oH[4];
    }
}

// ---------------------------------------------------------------------------
// Phase 2: GRU recurrence, f32x2 over k-pairs.
// 128 CTAs x 256 threads. CTA owns 2 batch rows; thread (j, h=tid>>7) covers
// k in [64h, 64h+64) as 32 k-pairs: 16 pairs of W in REGISTERS, 16 streamed
// from smem. hp broadcast via smem; cross-half gate reduction via smem.
// ---------------------------------------------------------------------------
__global__ __launch_bounds__(256) void recurrence2(
    const float* __restrict__ gi, const float* __restrict__ delta,
    const float* __restrict__ htil, const float* __restrict__ Whh,
    const float* __restrict__ bhh, float* __restrict__ Hraw)
{
    extern __shared__ float sm[];
    ull*   Ws  = reinterpret_cast<ull*>(sm);   // [3][32][128] k-pairs, 98304 B
    float* hpA = sm + 24576;                   // row0 h' [128]
    float* hpB = hpA + 128;                    // row1 h' [128]
    float* red = hpB + 128;                    // [2 rows][3 gates][128]

    const int tid = threadIdx.x;
    const int j = tid & 127;
    const int h = tid >> 7;

    // ---- fill streamed W (second 16 pairs of each half), pre-paired ----
    for (int s = tid; s < 3 * 32 * 128; s += 256) {
        int jj = s & 127, gsp = s >> 7;
        int g = gsp >> 5, sp = gsp & 31;
        int hh = sp >> 4, ii = sp & 15;
        Ws[s] = *reinterpret_cast<const ull*>(
            &Whh[(size_t)(g * 128 + jj) * 128 + 64 * hh + 32 + 2 * ii]);
    }
    // ---- register-resident W (first 16 pairs of my half) ----
    ull wr[16], wz[16], wn[16];
#pragma unroll
    for (int i = 0; i < 16; i++) {
        int k = 64 * h + 2 * i;
        wr[i] = *reinterpret_cast<const ull*>(&Whh[(size_t)(j) * 128 + k]);
        wz[i] = *reinterpret_cast<const ull*>(&Whh[(size_t)(128 + j) * 128 + k]);
        wn[i] = *reinterpret_cast<const ull*>(&Whh[(size_t)(256 + j) * 128 + k]);
    }
    const float br = bhh[j], bz = bhh[128 + j], bn = bhh[256 + j];

    const size_t base = ((size_t)blockIdx.x * 2 + h) * TR_;  // my row's time base
    float hreg = 0.f;
    // prefetch t = 0 (my row only)
    float d  = delta[base * 128 + j];
    float ht = htil[base * 128 + j];
    float gr = gi[base * 384 + j];
    float gz = gi[base * 384 + 128 + j];
    float gn = gi[base * 384 + 256 + j];
    __syncthreads();

    const ull* WsR = Ws + (0 * 32 + 16 * h) * 128 + j;   // stream i -> WsR[i*128]
    const ull* WsZ = Ws + (1 * 32 + 16 * h) * 128 + j;
    const ull* WsN = Ws + (2 * 32 + 16 * h) * 128 + j;
    float* myHp = h ? hpB : hpA;
    float* redW = red + (1 - h) * 3 * 128;   // write other row's partials
    float* redR = red + h * 3 * 128;         // read my row's partials
    const int kb = 64 * h;

    for (int t = 0; t < TR_; t++) {
        const float cgr = gr, cgz = gz, cgn = gn;
        const float hp = d * hreg + (1.f - d) * ht;
        myHp[j] = hp;
        __syncthreads();

        // prefetch t+1 (clamped; last-iter values unused)
        {
            int tn = (t + 1 < TR_) ? t + 1 : t;
            size_t o = base + tn;
            d  = delta[o * 128 + j];
            ht = htil[o * 128 + j];
            gr = gi[o * 384 + j];
            gz = gi[o * 384 + 128 + j];
            gn = gi[o * 384 + 256 + j];
        }

        ull ar0 = 0, az0 = 0, an0 = 0, ar1 = 0, az1 = 0, an1 = 0;
#pragma unroll
        for (int i = 0; i < 16; i++) {           // register-W pairs
            ull a0 = *reinterpret_cast<const ull*>(&hpA[kb + 2 * i]);
            ull a1 = *reinterpret_cast<const ull*>(&hpB[kb + 2 * i]);
            ar0 = fma2_(a0, wr[i], ar0); ar1 = fma2_(a1, wr[i], ar1);
            az0 = fma2_(a0, wz[i], az0); az1 = fma2_(a1, wz[i], az1);
            an0 = fma2_(a0, wn[i], an0); an1 = fma2_(a1, wn[i], an1);
        }
#pragma unroll
        for (int i = 0; i < 16; i++) {           // streamed-W pairs
            ull a0 = *reinterpret_cast<const ull*>(&hpA[kb + 32 + 2 * i]);
            ull a1 = *reinterpret_cast<const ull*>(&hpB[kb + 32 + 2 * i]);
            ull w0 = WsR[i * 128];
            ull w1 = WsZ[i * 128];
            ull w2 = WsN[i * 128];
            ar0 = fma2_(a0, w0, ar0); ar1 = fma2_(a1, w0, ar1);
            az0 = fma2_(a0, w1, az0); az1 = fma2_(a1, w1, az1);
            an0 = fma2_(a0, w2, an0); an1 = fma2_(a1, w2, an1);
        }
        // collapse even/odd lanes
        float2 p;
        p = unpack2_(ar0); float sR0 = p.x + p.y;
        p = unpack2_(az0); float sZ0 = p.x + p.y;
        p = unpack2_(an0); float sN0 = p.x + p.y;
        p = unpack2_(ar1); float sR1 = p.x + p.y;
        p = unpack2_(az1); float sZ1 = p.x + p.y;
        p = unpack2_(an1); float sN1 = p.x + p.y;

        float mR = h ? sR1 : sR0, mZ = h ? sZ1 : sZ0, mN = h ? sN1 : sN0;
        float oR = h ? sR0 : sR1, oZ = h ? sZ0 : sZ1, oN = h ? sN0 : sN1;
        redW[j] = oR; redW[128 + j] = oZ; redW[256 + j] = oN;
        __syncthreads();

        float ghr = mR + redR[j];
        float ghz = mZ + redR[128 + j];
        float ghn = mN + redR[256 + j];
        float r = sigmoidf_(cgr + ghr + br);
        float z = sigmoidf_(cgz + ghz + bz);
        float n = tanhf(cgn + r * (ghn + bn));
        hreg = (1.f - z) * n + z * hp;
        Hraw[(base + t) * 128 + j] = hreg;
    }
}

// ---------------------------------------------------------------------------
// Phase 3: gather + head MLP.  One warp per (b, ta); 8 warps/CTA share W1.
// ---------------------------------------------------------------------------
__global__ __launch_bounds__(256) void gather_head_kernel(
    const float* __restrict__ Hraw, const float* __restrict__ STD,
    const float* __restrict__ Z, const int* __restrict__ idx_map,
    const float* __restrict__ W1, const float* __restrict__ b1,
    const float* __restrict__ W2,
    float* __restrict__ eta, float* __restrict__ Hagg, float* __restrict__ maskO)
{
    extern __shared__ float sh[];
    float* W1s   = sh;                    // 64*176
    float* b1s   = W1s + HH_ * FD_;       // 64
    float* W2s   = b1s + HH_;             // 64
    float* feats = W2s + HH_;             // 8 * 184 (padded)

    const int tid = threadIdx.x;
    for (int s = tid; s < HH_ * FD_; s += 256) W1s[s] = W1[s];
    if (tid < HH_) { b1s[tid] = b1[tid]; W2s[tid] = W2[tid]; }
    __syncthreads();

    const int w = tid >> 5, lane = tid & 31;
    const int pair = blockIdx.x * 8 + w;      // 0 .. 16383
    const int b = pair >> 6, ta = pair & 63;

    const int idx = idx_map[b * TA_ + ta];
    const bool msk = idx >= 0;
    const int is = msk ? idx : 0;

    float* f = feats + w * 184;
    const float* hsrc = Hraw + ((size_t)b * TR_ + is) * H_;
    float4 hv = reinterpret_cast<const float4*>(hsrc)[lane];
    if (!msk) { hv.x = 0.f; hv.y = 0.f; hv.z = 0.f; hv.w = 0.f; }
    reinterpret_cast<float4*>(Hagg + ((size_t)b * TA_ + ta) * H_)[lane] = hv;
    reinterpret_cast<float4*>(f)[lane] = hv;
    f[128 + lane] = STD[(b * TA_ + ta) * PSTD_ + lane];
    if (lane < PSTA_) f[160 + lane] = Z[b * PSTA_ + lane];
    __syncwarp();

    float partial = 0.f;
#pragma unroll
    for (int jj0 = 0; jj0 < HH_; jj0 += 32) {
        int jj = jj0 + lane;
        float s = b1s[jj];
        const float* wrow = &W1s[jj * FD_];
#pragma unroll 8
        for (int k = 0; k < FD_; k++) s += f[k] * wrow[k];
        s = fmaxf(s, 0.f);
        partial += s * W2s[jj];
    }
#pragma unroll
    for (int o = 16; o; o >>= 1) partial += __shfl_xor_sync(0xffffffffu, partial, o);
    if (lane == 0) {
        eta[pair]   = partial;
        maskO[pair] = msk ? 1.f : 0.f;
    }
}

// ---------------------------------------------------------------------------
extern "C" void kernel_launch(void* const* d_in, const int* in_sizes, int n_in,
                              void* d_out, int out_size)
{
    const float* X     = (const float*)d_in[0];
    const float* M     = (const float*)d_in[1];
    const float* DT    = (const float*)d_in[2];
    const float* STD   = (const float*)d_in[3];
    const float* Z     = (const float*)d_in[4];
    const int*   idxm  = (const int*)  d_in[5];
    const float* xmean = (const float*)d_in[6];
    const float* Wd    = (const float*)d_in[7];
    const float* bd    = (const float*)d_in[8];
    const float* Wih   = (const float*)d_in[9];
    const float* bih   = (const float*)d_in[10];
    const float* Whh   = (const float*)d_in[11];
    const float* bhh   = (const float*)d_in[12];
    const float* W1    = (const float*)d_in[13];
    const float* b1    = (const float*)d_in[14];
    const float* W2    = (const float*)d_in[15];

    float* out   = (float*)d_out;
    float* eta   = out;                                    // 16384
    float* Hraw  = out + 16384;                            // 16,777,216
    float* Hagg  = out + 16384 + 16777216;                 // 2,097,152
    float* maskO = out + 16384 + 16777216 + 2097152;       // 16384

    float* scratch = nullptr;
    cudaGetSymbolAddress((void**)&scratch, g_scratch);
    float* xhat  = scratch;
    float* inp   = scratch + 16777216;
    float* htil  = scratch + 50331648;
    float* gi    = scratch + 67108864;
    float* delta = scratch + 117440512;

    // Phase 0
    prep_kernel<<<16384, 256>>>(X, M, DT, xmean, delta, xhat, inp);

    // Phase 1 (f32x2 packed GEMMs)
    sgemm2<1><<<dim3(1, 1024), 256>>>(xhat, Wd, bd, htil, 131072, 128, 128);
    sgemm2<0><<<dim3(3, 1024), 256>>>(inp, Wih, bih, gi, 131072, 384, 256);

    // Phase 2 (register-W + k-pair f32x2 recurrence)
    const int rec_smem = 98304 + (128 + 128 + 768) * (int)sizeof(float); // 102,400 B
    cudaFuncSetAttribute(recurrence2,
                         cudaFuncAttributeMaxDynamicSharedMemorySize, rec_smem);
    recurrence2<<<128, 256, rec_smem>>>(gi, delta, htil, Whh, bhh, Hraw);

    // Phase 3
    const int gh_smem = (HH_ * FD_ + HH_ + HH_ + 8 * 184) * (int)sizeof(float); // 51,456 B
    cudaFuncSetAttribute(gather_head_kernel,
                         cudaFuncAttributeMaxDynamicSharedMemorySize, gh_smem);
    gather_head_kernel<<<2048, 256, gh_smem>>>(Hraw, STD, Z, idxm, W1, b1, W2,
                                               eta, Hagg, maskO);
}

// round 9
// speedup vs baseline: 1.3944x; 1.0021x over previous
#include <cuda_runtime.h>
#include <cmath>

static constexpr int B_    = 256;
static constexpr int TR_   = 512;
static constexpr int H_    = 128;
static constexpr int TA_   = 64;
static constexpr int PSTD_ = 32;
static constexpr int PSTA_ = 16;
static constexpr int HH_   = 64;                 // head hidden
static constexpr int FD_   = H_ + PSTD_ + PSTA_; // 176

typedef unsigned long long ull;

// ---------------- packed-f32x2 helpers (dual-rate fp32 pipe) ----------------
__device__ __forceinline__ ull fma2_(ull a, ull b, ull c) {
    ull d;
    asm("fma.rn.f32x2 %0, %1, %2, %3;" : "=l"(d) : "l"(a), "l"(b), "l"(c));
    return d;
}
__device__ __forceinline__ ull splat2_(float x) {
    unsigned u = __float_as_uint(x);
    ull r;
    asm("mov.b64 %0, {%1, %1};" : "=l"(r) : "r"(u));
    return r;
}
__device__ __forceinline__ float2 unpack2_(ull v) {
    unsigned l, h;
    asm("mov.b64 {%0, %1}, %2;" : "=r"(l), "=r"(h) : "l"(v));
    return make_float2(__uint_as_float(l), __uint_as_float(h));
}

// ---------------- scratch (device global: allocation-free) ----------------
//   xhat  : [131072,128]  @ 0
//   inp   : [131072,256]  @ 16777216
//   htil  : [131072,128]  @ 50331648
//   gi    : [131072,384]  @ 67108864
//   delta : [131072,128]  @ 117440512
__device__ float g_scratch[134217728];

__device__ __forceinline__ float sigmoidf_(float x) { return 1.f / (1.f + expf(-x)); }

// ---------------------------------------------------------------------------
// Phase 0: elementwise prep.  delta = 1/(1+e^dt) (== exp(-softplus(dt)))
// ---------------------------------------------------------------------------
__global__ __launch_bounds__(256) void prep_kernel(
    const float* __restrict__ X, const float* __restrict__ M,
    const float* __restrict__ DT, const float* __restrict__ xmean,
    float* __restrict__ delta, float* __restrict__ xhat, float* __restrict__ inp)
{
    int i4 = blockIdx.x * blockDim.x + threadIdx.x;   // float4 index
    const float4 x4 = reinterpret_cast<const float4*>(X)[i4];
    const float4 m4 = reinterpret_cast<const float4*>(M)[i4];
    const float4 t4 = reinterpret_cast<const float4*>(DT)[i4];
    int row = i4 >> 5;
    int c4  = i4 & 31;
    const float4 xm4 = reinterpret_cast<const float4*>(xmean)[c4];

    float4 d4, xh4, xd4;
#pragma unroll
    for (int c = 0; c < 4; c++) {
        float x  = ((const float*)&x4)[c];
        float m  = ((const float*)&m4)[c];
        float dt = ((const float*)&t4)[c];
        float xm = ((const float*)&xm4)[c];
        float d  = 1.f / (1.f + expf(dt));
        float xh = m * x + (1.f - m) * xm;
        float xd = m * x + (1.f - m) * (d * xh + (1.f - d) * xm);
        ((float*)&d4)[c]  = d;
        ((float*)&xh4)[c] = xh;
        ((float*)&xd4)[c] = xd;
    }
    reinterpret_cast<float4*>(delta)[i4] = d4;
    reinterpret_cast<float4*>(xhat)[i4]  = xh4;
    reinterpret_cast<float4*>(inp)[row * 64 + c4]      = xd4;  // x_dec
    reinterpret_cast<float4*>(inp)[row * 64 + 32 + c4] = m4;   // m
}

// ---------------------------------------------------------------------------
// Phase 1: C[M,N] = A[M,K] @ Bw[N,K]^T + bias ; EPI=1 -> tanh epilogue
// BM=BN=128, BK=16, 256 threads, 8x8 microtile, f32x2 packed over row-pairs.
// ---------------------------------------------------------------------------
template <int EPI>
__global__ __launch_bounds__(256, 2) void sgemm2(
    const float* __restrict__ A, const float* __restrict__ Bw,
    const float* __restrict__ bias, float* __restrict__ C,
    int M, int N, int K)
{
    constexpr int BK = 16;
    __shared__ float As[BK][128];
    __shared__ float Bs[BK][128];

    const int bm = blockIdx.y * 128;
    const int bn = blockIdx.x * 128;
    const int tid = threadIdx.x;
    const int tr = (tid >> 4) << 3;       // 0..120 (mult of 8 -> 16B aligned)
    const int tc = (tid & 15) << 3;       // 0..120
    const int lRow = tid >> 2;            // 0..63
    const int lCol = (tid & 3) << 2;      // 0,4,8,12

    ull acc[4][8];                        // acc[i2][j] packs rows (tr+2*i2, tr+2*i2+1)
#pragma unroll
    for (int i = 0; i < 4; i++)
#pragma unroll
        for (int j = 0; j < 8; j++) acc[i][j] = 0ull;

    const float* Aptr = A + (size_t)bm * K;
    const float* Bptr = Bw + (size_t)bn * K;

    for (int k0 = 0; k0 < K; k0 += BK) {
#pragma unroll
        for (int h = 0; h < 2; h++) {
            int r = lRow + h * 64;
            float4 va = *reinterpret_cast<const float4*>(Aptr + (size_t)r * K + k0 + lCol);
            As[lCol + 0][r] = va.x; As[lCol + 1][r] = va.y;
            As[lCol + 2][r] = va.z; As[lCol + 3][r] = va.w;
            float4 vb = *reinterpret_cast<const float4*>(Bptr + (size_t)r * K + k0 + lCol);
            Bs[lCol + 0][r] = vb.x; Bs[lCol + 1][r] = vb.y;
            Bs[lCol + 2][r] = vb.z; Bs[lCol + 3][r] = vb.w;
        }
        __syncthreads();
#pragma unroll
        for (int k = 0; k < BK; k++) {
            // row pairs come packed straight out of the LDS.128s
            ulonglong2 aP0 = *reinterpret_cast<const ulonglong2*>(&As[k][tr]);
            ulonglong2 aP1 = *reinterpret_cast<const ulonglong2*>(&As[k][tr + 4]);
            float4 b0 = *reinterpret_cast<const float4*>(&Bs[k][tc]);
            float4 b1 = *reinterpret_cast<const float4*>(&Bs[k][tc + 4]);
            ull bb[8];
            bb[0] = splat2_(b0.x); bb[1] = splat2_(b0.y);
            bb[2] = splat2_(b0.z); bb[3] = splat2_(b0.w);
            bb[4] = splat2_(b1.x); bb[5] = splat2_(b1.y);
            bb[6] = splat2_(b1.z); bb[7] = splat2_(b1.w);
#pragma unroll
            for (int j = 0; j < 8; j++) {
                acc[0][j] = fma2_(aP0.x, bb[j], acc[0][j]);
                acc[1][j] = fma2_(aP0.y, bb[j], acc[1][j]);
                acc[2][j] = fma2_(aP1.x, bb[j], acc[2][j]);
                acc[3][j] = fma2_(aP1.y, bb[j], acc[3][j]);
            }
        }
        __syncthreads();
    }

    float bv[8];
    *(float4*)&bv[0] = *(const float4*)&bias[bn + tc];
    *(float4*)&bv[4] = *(const float4*)&bias[bn + tc + 4];
#pragma unroll
    for (int i2 = 0; i2 < 4; i2++) {
        float oL[8], oH[8];
#pragma unroll
        for (int j = 0; j < 8; j++) {
            float2 p = unpack2_(acc[i2][j]);
            float vl = p.x + bv[j];
            float vh = p.y + bv[j];
            oL[j] = EPI ? tanhf(vl) : vl;
            oH[j] = EPI ? tanhf(vh) : vh;
        }
        float* crowL = C + (size_t)(bm + tr + 2 * i2 + 0) * N + bn + tc;
        float* crowH = C + (size_t)(bm + tr + 2 * i2 + 1) * N + bn + tc;
        *(float4*)&crowL[0] = *(float4*)&oL[0];
        *(float4*)&crowL[4] = *(float4*)&oL[4];
        *(float4*)&crowH[0] = *(float4*)&oH[0];
        *(float4*)&crowH[4] = *(float4*)&oH[4];
    }
}

// ---------------------------------------------------------------------------
// Phase 2: GRU recurrence, f32x2 over k-pairs.
// 128 CTAs x 256 threads. CTA owns 2 batch rows; thread (j, h=tid>>7) covers
// k in [64h, 64h+64) as 32 k-pairs: 16 pairs of W in REGISTERS, 16 streamed
// from smem. hp broadcast via smem; cross-half gate reduction via smem.
// ---------------------------------------------------------------------------
__global__ __launch_bounds__(256) void recurrence2(
    const float* __restrict__ gi, const float* __restrict__ delta,
    const float* __restrict__ htil, const float* __restrict__ Whh,
    const float* __restrict__ bhh, float* __restrict__ Hraw)
{
    extern __shared__ float sm[];
    ull*   Ws  = reinterpret_cast<ull*>(sm);   // [3][32][128] k-pairs, 98304 B
    float* hpA = sm + 24576;                   // row0 h' [128]
    float* hpB = hpA + 128;                    // row1 h' [128]
    float* red = hpB + 128;                    // [2 rows][3 gates][128]

    const int tid = threadIdx.x;
    const int j = tid & 127;
    const int h = tid >> 7;

    // ---- fill streamed W (second 16 pairs of each half), pre-paired ----
    for (int s = tid; s < 3 * 32 * 128; s += 256) {
        int jj = s & 127, gsp = s >> 7;
        int g = gsp >> 5, sp = gsp & 31;
        int hh = sp >> 4, ii = sp & 15;
        Ws[s] = *reinterpret_cast<const ull*>(
            &Whh[(size_t)(g * 128 + jj) * 128 + 64 * hh + 32 + 2 * ii]);
    }
    // ---- register-resident W (first 16 pairs of my half) ----
    ull wr[16], wz[16], wn[16];
#pragma unroll
    for (int i = 0; i < 16; i++) {
        int k = 64 * h + 2 * i;
        wr[i] = *reinterpret_cast<const ull*>(&Whh[(size_t)(j) * 128 + k]);
        wz[i] = *reinterpret_cast<const ull*>(&Whh[(size_t)(128 + j) * 128 + k]);
        wn[i] = *reinterpret_cast<const ull*>(&Whh[(size_t)(256 + j) * 128 + k]);
    }
    const float br = bhh[j], bz = bhh[128 + j], bn = bhh[256 + j];

    const size_t base = ((size_t)blockIdx.x * 2 + h) * TR_;  // my row's time base
    float hreg = 0.f;
    // prefetch t = 0 (my row only)
    float d  = delta[base * 128 + j];
    float ht = htil[base * 128 + j];
    float gr = gi[base * 384 + j];
    float gz = gi[base * 384 + 128 + j];
    float gn = gi[base * 384 + 256 + j];
    __syncthreads();

    const ull* WsR = Ws + (0 * 32 + 16 * h) * 128 + j;   // stream i -> WsR[i*128]
    const ull* WsZ = Ws + (1 * 32 + 16 * h) * 128 + j;
    const ull* WsN = Ws + (2 * 32 + 16 * h) * 128 + j;
    float* myHp = h ? hpB : hpA;
    float* redW = red + (1 - h) * 3 * 128;   // write other row's partials
    float* redR = red + h * 3 * 128;         // read my row's partials
    const int kb = 64 * h;

    for (int t = 0; t < TR_; t++) {
        const float cgr = gr, cgz = gz, cgn = gn;
        const float hp = d * hreg + (1.f - d) * ht;
        myHp[j] = hp;
        __syncthreads();

        // prefetch t+1 (clamped; last-iter values unused)
        {
            int tn = (t + 1 < TR_) ? t + 1 : t;
            size_t o = base + tn;
            d  = delta[o * 128 + j];
            ht = htil[o * 128 + j];
            gr = gi[o * 384 + j];
            gz = gi[o * 384 + 128 + j];
            gn = gi[o * 384 + 256 + j];
        }

        ull ar0 = 0, az0 = 0, an0 = 0, ar1 = 0, az1 = 0, an1 = 0;
#pragma unroll
        for (int i = 0; i < 16; i++) {           // register-W pairs
            ull a0 = *reinterpret_cast<const ull*>(&hpA[kb + 2 * i]);
            ull a1 = *reinterpret_cast<const ull*>(&hpB[kb + 2 * i]);
            ar0 = fma2_(a0, wr[i], ar0); ar1 = fma2_(a1, wr[i], ar1);
            az0 = fma2_(a0, wz[i], az0); az1 = fma2_(a1, wz[i], az1);
            an0 = fma2_(a0, wn[i], an0); an1 = fma2_(a1, wn[i], an1);
        }
#pragma unroll
        for (int i = 0; i < 16; i++) {           // streamed-W pairs
            ull a0 = *reinterpret_cast<const ull*>(&hpA[kb + 32 + 2 * i]);
            ull a1 = *reinterpret_cast<const ull*>(&hpB[kb + 32 + 2 * i]);
            ull w0 = WsR[i * 128];
            ull w1 = WsZ[i * 128];
            ull w2 = WsN[i * 128];
            ar0 = fma2_(a0, w0, ar0); ar1 = fma2_(a1, w0, ar1);
            az0 = fma2_(a0, w1, az0); az1 = fma2_(a1, w1, az1);
            an0 = fma2_(a0, w2, an0); an1 = fma2_(a1, w2, an1);
        }
        // collapse even/odd lanes
        float2 p;
        p = unpack2_(ar0); float sR0 = p.x + p.y;
        p = unpack2_(az0); float sZ0 = p.x + p.y;
        p = unpack2_(an0); float sN0 = p.x + p.y;
        p = unpack2_(ar1); float sR1 = p.x + p.y;
        p = unpack2_(az1); float sZ1 = p.x + p.y;
        p = unpack2_(an1); float sN1 = p.x + p.y;

        float mR = h ? sR1 : sR0, mZ = h ? sZ1 : sZ0, mN = h ? sN1 : sN0;
        float oR = h ? sR0 : sR1, oZ = h ? sZ0 : sZ1, oN = h ? sN0 : sN1;
        redW[j] = oR; redW[128 + j] = oZ; redW[256 + j] = oN;
        __syncthreads();

        float ghr = mR + redR[j];
        float ghz = mZ + redR[128 + j];
        float ghn = mN + redR[256 + j];
        float r = sigmoidf_(cgr + ghr + br);
        float z = sigmoidf_(cgz + ghz + bz);
        float n = tanhf(cgn + r * (ghn + bn));
        hreg = (1.f - z) * n + z * hp;
        Hraw[(base + t) * 128 + j] = hreg;
    }
}

// ---------------------------------------------------------------------------
// Phase 3: gather + head MLP.  One warp per (b, ta); 8 warps/CTA share W1.
// ---------------------------------------------------------------------------
__global__ __launch_bounds__(256) void gather_head_kernel(
    const float* __restrict__ Hraw, const float* __restrict__ STD,
    const float* __restrict__ Z, const int* __restrict__ idx_map,
    const float* __restrict__ W1, const float* __restrict__ b1,
    const float* __restrict__ W2,
    float* __restrict__ eta, float* __restrict__ Hagg, float* __restrict__ maskO)
{
    extern __shared__ float sh[];
    float* W1s   = sh;                    // 64*176
    float* b1s   = W1s + HH_ * FD_;       // 64
    float* W2s   = b1s + HH_;             // 64
    float* feats = W2s + HH_;             // 8 * 184 (padded)

    const int tid = threadIdx.x;
    for (int s = tid; s < HH_ * FD_; s += 256) W1s[s] = W1[s];
    if (tid < HH_) { b1s[tid] = b1[tid]; W2s[tid] = W2[tid]; }
    __syncthreads();

    const int w = tid >> 5, lane = tid & 31;
    const int pair = blockIdx.x * 8 + w;      // 0 .. 16383
    const int b = pair >> 6, ta = pair & 63;

    const int idx = idx_map[b * TA_ + ta];
    const bool msk = idx >= 0;
    const int is = msk ? idx : 0;

    float* f = feats + w * 184;
    const float* hsrc = Hraw + ((size_t)b * TR_ + is) * H_;
    float4 hv = reinterpret_cast<const float4*>(hsrc)[lane];
    if (!msk) { hv.x = 0.f; hv.y = 0.f; hv.z = 0.f; hv.w = 0.f; }
    reinterpret_cast<float4*>(Hagg + ((size_t)b * TA_ + ta) * H_)[lane] = hv;
    reinterpret_cast<float4*>(f)[lane] = hv;
    f[128 + lane] = STD[(b * TA_ + ta) * PSTD_ + lane];
    if (lane < PSTA_) f[160 + lane] = Z[b * PSTA_ + lane];
    __syncwarp();

    float partial = 0.f;
#pragma unroll
    for (int jj0 = 0; jj0 < HH_; jj0 += 32) {
        int jj = jj0 + lane;
        float s = b1s[jj];
        const float* wrow = &W1s[jj * FD_];
#pragma unroll 8
        for (int k = 0; k < FD_; k++) s += f[k] * wrow[k];
        s = fmaxf(s, 0.f);
        partial += s * W2s[jj];
    }
#pragma unroll
    for (int o = 16; o; o >>= 1) partial += __shfl_xor_sync(0xffffffffu, partial, o);
    if (lane == 0) {
        eta[pair]   = partial;
        maskO[pair] = msk ? 1.f : 0.f;
    }
}

// ---------------------------------------------------------------------------
extern "C" void kernel_launch(void* const* d_in, const int* in_sizes, int n_in,
                              void* d_out, int out_size)
{
    const float* X     = (const float*)d_in[0];
    const float* M     = (const float*)d_in[1];
    const float* DT    = (const float*)d_in[2];
    const float* STD   = (const float*)d_in[3];
    const float* Z     = (const float*)d_in[4];
    const int*   idxm  = (const int*)  d_in[5];
    const float* xmean = (const float*)d_in[6];
    const float* Wd    = (const float*)d_in[7];
    const float* bd    = (const float*)d_in[8];
    const float* Wih   = (const float*)d_in[9];
    const float* bih   = (const float*)d_in[10];
    const float* Whh   = (const float*)d_in[11];
    const float* bhh   = (const float*)d_in[12];
    const float* W1    = (const float*)d_in[13];
    const float* b1    = (const float*)d_in[14];
    const float* W2    = (const float*)d_in[15];

    float* out   = (float*)d_out;
    float* eta   = out;                                    // 16384
    float* Hraw  = out + 16384;                            // 16,777,216
    float* Hagg  = out + 16384 + 16777216;                 // 2,097,152
    float* maskO = out + 16384 + 16777216 + 2097152;       // 16384

    float* scratch = nullptr;
    cudaGetSymbolAddress((void**)&scratch, g_scratch);
    float* xhat  = scratch;
    float* inp   = scratch + 16777216;
    float* htil  = scratch + 50331648;
    float* gi    = scratch + 67108864;
    float* delta = scratch + 117440512;

    // Phase 0
    prep_kernel<<<16384, 256>>>(X, M, DT, xmean, delta, xhat, inp);

    // Phase 1 (f32x2 packed GEMMs)
    sgemm2<1><<<dim3(1, 1024), 256>>>(xhat, Wd, bd, htil, 131072, 128, 128);
    sgemm2<0><<<dim3(3, 1024), 256>>>(inp, Wih, bih, gi, 131072, 384, 256);

    // Phase 2 (register-W + k-pair f32x2 recurrence)
    const int rec_smem = 98304 + (128 + 128 + 768) * (int)sizeof(float); // 102,400 B
    cudaFuncSetAttribute(recurrence2,
                         cudaFuncAttributeMaxDynamicSharedMemorySize, rec_smem);
    recurrence2<<<128, 256, rec_smem>>>(gi, delta, htil, Whh, bhh, Hraw);

    // Phase 3
    const int gh_smem = (HH_ * FD_ + HH_ + HH_ + 8 * 184) * (int)sizeof(float); // 51,456 B
    cudaFuncSetAttribute(gather_head_kernel,
                         cudaFuncAttributeMaxDynamicSharedMemorySize, gh_smem);
    gather_head_kernel<<<2048, 256, gh_smem>>>(Hraw, STD, Z, idxm, W1, b1, W2,
                                               eta, Hagg, maskO);
}